// round 14
// baseline (speedup 1.0000x reference)
#include <cuda_runtime.h>
#include <cstdint>

// ---------------- problem constants ----------------
#define NN 16
#define CC 64
#define HW 3136       // 56*56
#define WID 56

// ---------------- device scratch ----------------
__device__ float g_maxabs_x, g_maxw1, g_maxw2, g_max_r1, g_max_r2;
__device__ float g_part[512];
__device__ unsigned g_qxp[NN*16*HW];     // packed int8 qx: (n, c4, hw), byte j = channel 4*c4+j
__device__ unsigned g_q1p[NN*16*HW];     // packed uint8 q1
__device__ float    g_t1 [NN*CC*HW];     // bn1 output (pre-relu), fp32
__device__ unsigned g_qw1p[9216];        // packed weights: [c4][pos][o]
__device__ unsigned g_qw2p[9216];
__device__ int g_wsum1[4608], g_wsum2[4608];     // [cb][pos], cb = c*8+bit
__device__ int g_stats1[9*512], g_stats2[9*512]; // 9 stats x 512 channel-bits

__device__ __forceinline__ void atomicMaxF(float* a, float v) {
    atomicMax((int*)a, __float_as_int(v));   // valid for non-negative floats
}
__device__ __forceinline__ float warpMaxPos(float v) {
    return __uint_as_float(__reduce_max_sync(0xffffffffu, __float_as_uint(v)));
}

// int8 tensor-core mma: D(16x8,s32) += A(16x32) * B(32x8)
template<int PASS>
__device__ __forceinline__ void MMA8(int* c, unsigned a0, unsigned a1, unsigned a2, unsigned a3,
                                     unsigned b0, unsigned b1) {
    if (PASS == 1)
        asm volatile(
            "mma.sync.aligned.m16n8k32.row.col.s32.s8.s8.s32 "
            "{%0,%1,%2,%3},{%4,%5,%6,%7},{%8,%9},{%0,%1,%2,%3};"
            : "+r"(c[0]), "+r"(c[1]), "+r"(c[2]), "+r"(c[3])
            : "r"(a0), "r"(a1), "r"(a2), "r"(a3), "r"(b0), "r"(b1));
    else
        asm volatile(
            "mma.sync.aligned.m16n8k32.row.col.s32.u8.s8.s32 "
            "{%0,%1,%2,%3},{%4,%5,%6,%7},{%8,%9},{%0,%1,%2,%3};"
            : "+r"(c[0]), "+r"(c[1]), "+r"(c[2]), "+r"(c[3])
            : "r"(a0), "r"(a1), "r"(a2), "r"(a3), "r"(b0), "r"(b1));
}

// ---------------- reduceA: partial max|x| (0..511), max|w| (512,513), init (514)
__global__ void reduceA(const float4* __restrict__ x,
                        const float* __restrict__ w1, const float* __restrict__ w2) {
    int b = blockIdx.x;
    if (b == 514) {
        if (threadIdx.x == 0) { g_max_r1 = 0.f; g_max_r2 = 0.f; }
        for (int i = threadIdx.x; i < 4608; i += 256) { g_stats1[i] = 0; g_stats2[i] = 0; }
        return;
    }
    float m = 0.f;
    if (b < 512) {
        const int n4 = NN*CC*HW/4;
        for (int i = b*256 + threadIdx.x; i < n4; i += 512*256) {
            float4 v = x[i];
            m = fmaxf(m, fmaxf(fmaxf(fabsf(v.x), fabsf(v.y)), fmaxf(fabsf(v.z), fabsf(v.w))));
        }
    } else {
        const float* w = (b == 513) ? w2 : w1;
        for (int i = threadIdx.x; i < 36864; i += 256) m = fmaxf(m, fabsf(w[i]));
    }
    m = warpMaxPos(m);
    __shared__ float sm[8];
    if ((threadIdx.x & 31) == 0) sm[threadIdx.x >> 5] = m;
    __syncthreads();
    if (threadIdx.x == 0) {
        float mm = sm[0];
        #pragma unroll
        for (int i = 1; i < 8; i++) mm = fmaxf(mm, sm[i]);
        if (b < 512) g_part[b] = mm;
        else if (b == 512) g_maxw1 = mm;
        else g_maxw2 = mm;
    }
}

// ---------------- fused quantize + bit stats (+ weight wsum blocks on PASS 1) --
// Nibble-packed counters (mask 0x11111111): per-thread nibble totals <= 8 < 15.
template<int PASS>
__global__ void __launch_bounds__(256) quantStatsKernel(const float* __restrict__ xin,
                                                        const float* __restrict__ w1,
                                                        const float* __restrict__ w2) {
    cudaGridDependencySynchronize();
    const unsigned M = 0x01010101u;
    const unsigned N4 = 0x11111111u;
    if (PASS == 1 && blockIdx.x >= 512) {
        int item = (blockIdx.x - 512)*8 + (threadIdx.x >> 5);
        int lane = threadIdx.x & 31;
        int sel = item / 144;
        int g   = item - sel*144;
        int c4  = g / 9, pos = g - c4*9;
        const float* w = sel ? w2 : w1;
        float s = (sel ? g_maxw2 : g_maxw1) * (1.0f/127.0f);
        unsigned* wpout = sel ? g_qw2p : g_qw1p;
        unsigned wds[2];
        #pragma unroll
        for (int h = 0; h < 2; h++) {
            int o = lane + 32*h;
            unsigned word = 0;
            #pragma unroll
            for (int j = 0; j < 4; j++) {
                float q = rintf(w[o*576 + (c4*4 + j)*9 + pos] / s);
                q = fminf(127.f, fmaxf(-127.f, q));
                word |= (((unsigned)(int)q) & 0xffu) << (8*j);
            }
            wpout[c4*576 + pos*64 + o] = word;
            wds[h] = word;
        }
        unsigned acc[8];
        #pragma unroll
        for (int k = 0; k < 8; k++)
            acc[k] = __reduce_add_sync(0xffffffffu, ((wds[0] >> k) & M) + ((wds[1] >> k) & M));
        int j = lane >> 3, k = lane & 7;
        int* wsum = sel ? g_wsum2 : g_wsum1;
        wsum[((c4*4 + j)*8 + k)*9 + pos] = (int)((acc[k] >> (8*j)) & 0xffu);
        return;
    }

    int n    = blockIdx.x >> 5;
    int rem  = blockIdx.x & 31;
    int c4   = rem >> 1;
    int half = rem & 1;
    const float* src = (PASS == 1) ? xin : (const float*)g_t1;
    const float4* s0 = (const float4*)(src + (size_t)(n*CC + c4*4)*HW);
    unsigned* qp = (PASS == 1) ? g_qxp : g_q1p;
    uint4* dst = (uint4*)(qp + (size_t)(n*16 + c4)*HW);

    __shared__ unsigned scCor[128];
    __shared__ unsigned ws[8*48];
    __shared__ float sMaxW[8];

    if (PASS == 1) {
        float mloc = 0.f;
        for (int i = threadIdx.x; i < 512; i += 256) mloc = fmaxf(mloc, g_part[i]);
        mloc = warpMaxPos(mloc);
        if ((threadIdx.x & 31) == 0) sMaxW[threadIdx.x >> 5] = mloc;
    }
    if (threadIdx.x < 128) scCor[threadIdx.x] = 0;
    __syncthreads();

    float s;
    if (PASS == 1) {
        float mm = sMaxW[0];
        #pragma unroll
        for (int i = 1; i < 8; i++) mm = fmaxf(mm, sMaxW[i]);
        if (blockIdx.x == 0 && threadIdx.x == 0) g_maxabs_x = mm;
        s = mm * (1.0f/127.0f);
    } else {
        s = g_max_r1 * (1.0f/255.0f);
    }
    float sinv = 1.0f / s;

    auto qByte = [&](float v) -> unsigned {
        int q;
        if (PASS == 1) {
            q = __float2int_rn(v * sinv);
            q = ::max(-127, ::min(127, q));
        } else {
            q = __float2int_rn(fmaxf(v, 0.f) * sinv);
            q = ::min(255, q);
        }
        return (unsigned)q & 0xffu;
    };
    auto quantFromF = [&](const float4 f[4], unsigned w[4]) {
        w[0] = qByte(f[0].x) | (qByte(f[1].x) << 8) | (qByte(f[2].x) << 16) | (qByte(f[3].x) << 24);
        w[1] = qByte(f[0].y) | (qByte(f[1].y) << 8) | (qByte(f[2].y) << 16) | (qByte(f[3].y) << 24);
        w[2] = qByte(f[0].z) | (qByte(f[1].z) << 8) | (qByte(f[2].z) << 16) | (qByte(f[3].z) << 24);
        w[3] = qByte(f[0].w) | (qByte(f[1].w) << 8) | (qByte(f[2].w) << 16) | (qByte(f[3].w) << 24);
    };
    auto quantQuad = [&](int i, unsigned w[4]) {
        float4 f[4];
        f[0] = s0[i]; f[1] = s0[784 + i]; f[2] = s0[1568 + i]; f[3] = s0[2352 + i];
        quantFromF(f, w);
    };

    // -------- main loop: 2-quad explicit ILP (indices tid and tid+256) --------
    unsigned accN[4] = {0,0,0,0};
    int ibase = half * 392;
    {
        int li0 = threadIdx.x;
        int i0 = ibase + li0;
        bool has2 = (li0 + 256) < 392;
        int i1 = i0 + 256;
        float4 fA[4], fB[4];
        fA[0] = s0[i0]; fA[1] = s0[784 + i0]; fA[2] = s0[1568 + i0]; fA[3] = s0[2352 + i0];
        if (has2) {
            fB[0] = s0[i1]; fB[1] = s0[784 + i1]; fB[2] = s0[1568 + i1]; fB[3] = s0[2352 + i1];
        }
        unsigned w[4];
        quantFromF(fA, w);
        dst[i0] = make_uint4(w[0], w[1], w[2], w[3]);
        #pragma unroll
        for (int k = 0; k < 4; k++)
            accN[k] += ((w[0]>>k)&N4) + ((w[1]>>k)&N4) + ((w[2]>>k)&N4) + ((w[3]>>k)&N4);
        if (has2) {
            quantFromF(fB, w);
            dst[i1] = make_uint4(w[0], w[1], w[2], w[3]);
            #pragma unroll
            for (int k = 0; k < 4; k++)
                accN[k] += ((w[0]>>k)&N4) + ((w[1]>>k)&N4) + ((w[2]>>k)&N4) + ((w[3]>>k)&N4);
        }
    }

    // -------- borders: warp 0 = row border, warp 1 = col 0, warp 2 = col 55 ---
    unsigned aBN[4] = {0,0,0,0};
    int warp = threadIdx.x >> 5;
    int lane = threadIdx.x & 31;
    if (warp == 0 && lane < 14) {
        int i = half ? 770 + lane : lane;
        unsigned w[4];
        quantQuad(i, w);
        #pragma unroll
        for (int k = 0; k < 4; k++)
            aBN[k] += ((w[0]>>k)&N4) + ((w[1]>>k)&N4) + ((w[2]>>k)&N4) + ((w[3]>>k)&N4);
        if (lane == 0) {
            int corner = half ? 2 : 0;  unsigned u = w[0];
            #pragma unroll
            for (int l = 0; l < 32; l++) atomicAdd(&scCor[corner*32 + l], (u >> l) & 1u);
        }
        if (lane == 13) {
            int corner = half ? 3 : 1;  unsigned u = w[3];
            #pragma unroll
            for (int l = 0; l < 32; l++) atomicAdd(&scCor[corner*32 + l], (u >> l) & 1u);
        }
    } else if (warp == 1 && lane < 28) {
        int i = ibase + lane*14;
        unsigned w[4];
        quantQuad(i, w);
        #pragma unroll
        for (int k = 0; k < 4; k++) aBN[k] += (w[0] >> k) & N4;
    } else if (warp == 2 && lane < 28) {
        int i = ibase + lane*14 + 13;
        unsigned w[4];
        quantQuad(i, w);
        #pragma unroll
        for (int k = 0; k < 4; k++) aBN[k] += (w[3] >> k) & N4;
    }

    // unpack nibbles -> byte lanes (<=8), then 16-bit split + REDUX
    unsigned aLo[8], aHi[8], aB[8];
    #pragma unroll
    for (int k = 0; k < 4; k++) {
        unsigned lo = accN[k] & 0x0F0F0F0Fu;
        unsigned hi = (accN[k] >> 4) & 0x0F0F0F0Fu;
        aLo[k]   = __reduce_add_sync(0xffffffffu, lo & 0x00FF00FFu);
        aHi[k]   = __reduce_add_sync(0xffffffffu, (lo >> 8) & 0x00FF00FFu);
        aLo[k+4] = __reduce_add_sync(0xffffffffu, hi & 0x00FF00FFu);
        aHi[k+4] = __reduce_add_sync(0xffffffffu, (hi >> 8) & 0x00FF00FFu);
        aB[k]    = __reduce_add_sync(0xffffffffu, aBN[k] & 0x0F0F0F0Fu);
        aB[k+4]  = __reduce_add_sync(0xffffffffu, (aBN[k] >> 4) & 0x0F0F0F0Fu);
    }
    if (lane == 0) {
        #pragma unroll
        for (int k = 0; k < 8; k++) {
            ws[warp*48 +     k] = aLo[k];
            ws[warp*48 + 8 + k] = aHi[k];
        }
        #pragma unroll
        for (int slot = 0; slot < 4; slot++)
            #pragma unroll
            for (int k = 0; k < 8; k++) ws[warp*48 + 16 + slot*8 + k] = 0;
        int region = (warp == 0) ? (half ? 2 : 1) : (warp == 1) ? 3 : (warp == 2) ? 4 : 0;
        if (region) {
            #pragma unroll
            for (int k = 0; k < 8; k++) ws[warp*48 + 16 + (region-1)*8 + k] = aB[k];
        }
    }
    __syncthreads();

    int* stats = (PASS == 1) ? g_stats1 : g_stats2;
    if (threadIdx.x < 8) {
        int k = threadIdx.x;
        unsigned vlo = 0, vhi = 0;
        #pragma unroll
        for (int wp = 0; wp < 8; wp++) {
            vlo += ws[wp*48 +     k];
            vhi += ws[wp*48 + 8 + k];
        }
        atomicAdd(&stats[(c4*4 + 0)*8 + k], (int)(vlo & 0xffffu));
        atomicAdd(&stats[(c4*4 + 2)*8 + k], (int)(vlo >> 16));
        atomicAdd(&stats[(c4*4 + 1)*8 + k], (int)(vhi & 0xffffu));
        atomicAdd(&stats[(c4*4 + 3)*8 + k], (int)(vhi >> 16));
    } else if (threadIdx.x < 40) {
        int t2   = threadIdx.x - 8;
        int sidx = 1 + (t2 >> 3);
        int k    = t2 & 7;
        unsigned v = 0;
        #pragma unroll
        for (int wp = 0; wp < 8; wp++) v += ws[wp*48 + 8 + sidx*8 + k];
        #pragma unroll
        for (int j = 0; j < 4; j++)
            atomicAdd(&stats[sidx*512 + (c4*4 + j)*8 + k], (int)((v >> (8*j)) & 0xffu));
    }
    if (threadIdx.x < 128) {
        int corner = threadIdx.x >> 5;
        int l = threadIdx.x & 31;
        int j = l >> 3, k = l & 7;
        int v = (int)scCor[threadIdx.x];
        if (v) atomicAdd(&stats[(5 + corner)*512 + (c4*4 + j)*8 + k], v);
    }
}

// ---------------- int8 TENSOR-CORE conv (mma.sync m16n8k32) + BN (+identity) ----
// __launch_bounds__(224, 3): force 3 blocks/SM (reg cap ~97) so the 448-block
// grid runs as ~one wave instead of 2 (2 blocks/SM -> 296+152 waves).
template<int PASS>
__global__ void __launch_bounds__(224, 3) convKernel(
    const float* __restrict__ gamma, const float* __restrict__ beta,
    const float* __restrict__ mean,  const float* __restrict__ var,
    float* __restrict__ dOut)
{
    cudaGridDependencySynchronize();
    const unsigned* __restrict__ inP = (PASS == 1) ? g_qxp : g_q1p;
    const unsigned* __restrict__ wP  = (PASS == 1) ? g_qw1p : g_qw2p;
    int n  = blockIdx.x / 28;
    int h0 = (blockIdx.x - n*28) * 2;

    extern __shared__ unsigned dynS[];
    unsigned* sW  = dynS;            // 16*584 = 9344 words (transposed weights)
    unsigned* sIn = dynS + 9344;     // 16*232 = 3712 words
    __shared__ float sAc[64], sBc[64];
    __shared__ float smx[7];

    int tid  = threadIdx.x;
    int lane = tid & 31, wid = tid >> 5;
    int gid  = lane >> 2, t4 = lane & 3;
    int w0   = wid * 8;

    float sp1, sx = 0.f;
    if (PASS == 1) {
        sp1 = (g_maxabs_x * (1.f/127.f)) * (g_maxw1 * (1.f/127.f));
    } else {
        sp1 = (g_max_r1 * (1.f/255.f)) * (g_maxw2 * (1.f/127.f));
        sx  = g_maxabs_x * (1.f/127.f);
    }
    if (tid < 64) {
        float inv = gamma[tid] / sqrtf(var[tid] + 1e-5f);
        sAc[tid] = sp1 * inv;
        sBc[tid] = beta[tid] - mean[tid]*inv;
    }

    // stage weights transposed: dest word = c4*584 + pos*64 + (o&7)*8 + (o>>3)
    {
        const uint4* wp4 = (const uint4*)wP;
        for (int i4 = tid; i4 < 2304; i4 += 224) {
            int i = i4 << 2;
            int o = i & 63;
            int cp = i >> 6;
            int c4l = cp / 9;
            int pos = cp - c4l*9;
            uint4 v = wp4[i4];
            unsigned base = c4l*584 + pos*64 + (o >> 3);
            int og = o & 7;      // 0 or 4
            sW[base + (og + 0)*8] = v.x;
            sW[base + (og + 1)*8] = v.y;
            sW[base + (og + 2)*8] = v.z;
            sW[base + (og + 3)*8] = v.w;
        }
    }
    // stage input tile (rows h0-1 .. h0+2 with halo)
    for (int p = tid; p < 3712; p += 224) {
        int c4r = p / 58;
        int cc  = p - c4r*58;
        int rr  = c4r & 3;
        int c4l = c4r >> 2;
        int gr = h0 - 1 + rr, gc = cc - 1;
        unsigned v = 0;
        if ((unsigned)gr < 56u && (unsigned)gc < 56u)
            v = inP[(n*16 + c4l)*HW + gr*WID + gc];
        sIn[c4l*232 + rr*58 + cc] = v;
    }
    __syncthreads();

    int acc[8][4];
    #pragma unroll
    for (int nt = 0; nt < 8; nt++)
        #pragma unroll
        for (int r = 0; r < 4; r++) acc[nt][r] = 0;

    #pragma unroll
    for (int cg = 0; cg < 2; cg++) {
        int cb = cg * 8;
        #pragma unroll
        for (int ph = 0; ph < 3; ph++) {
            #pragma unroll
            for (int pw = 0; pw < 3; pw++) {
                int pos = ph*3 + pw;
                int ccol = w0 + gid + pw;
                unsigned a0 = sIn[(cb + t4    )*232 +  ph   *58 + ccol];
                unsigned a1 = sIn[(cb + t4    )*232 + (ph+1)*58 + ccol];
                unsigned a2 = sIn[(cb + 4 + t4)*232 +  ph   *58 + ccol];
                unsigned a3 = sIn[(cb + 4 + t4)*232 + (ph+1)*58 + ccol];
                const uint4* pb0 = (const uint4*)(sW + (cb + t4    )*584 + pos*64 + gid*8);
                const uint4* pb1 = (const uint4*)(sW + (cb + 4 + t4)*584 + pos*64 + gid*8);
                uint4 b0lo = pb0[0], b0hi = pb0[1];
                uint4 b1lo = pb1[0], b1hi = pb1[1];
                unsigned b0a[8] = {b0lo.x, b0lo.y, b0lo.z, b0lo.w, b0hi.x, b0hi.y, b0hi.z, b0hi.w};
                unsigned b1a[8] = {b1lo.x, b1lo.y, b1lo.z, b1lo.w, b1hi.x, b1hi.y, b1hi.z, b1hi.w};
                #pragma unroll
                for (int nt = 0; nt < 8; nt++)
                    MMA8<PASS>(acc[nt], a0, a1, a2, a3, b0a[nt], b1a[nt]);
            }
        }
    }

    // epilogue: BN (+identity), store, max
    float* dstp = (PASS == 1) ? g_t1 : dOut;
    int hw0 = h0*WID + w0 + gid;
    int hw1 = hw0 + WID;
    float mx = 0.f;
    #pragma unroll
    for (int nt = 0; nt < 8; nt++) {
        int o0 = nt*8 + t4*2;
        float A0 = sAc[o0],   B0 = sBc[o0];
        float A1 = sAc[o0+1], B1 = sBc[o0+1];
        float t00 = (float)acc[nt][0] * A0 + B0;
        float t01 = (float)acc[nt][1] * A1 + B1;
        float t10 = (float)acc[nt][2] * A0 + B0;
        float t11 = (float)acc[nt][3] * A1 + B1;
        if (PASS == 2) {
            int c4i = o0 >> 2;
            int sh  = (o0 & 3) * 8;
            unsigned id0 = g_qxp[(n*16 + c4i)*HW + hw0];
            unsigned id1 = g_qxp[(n*16 + c4i)*HW + hw1];
            t00 += (float)((int)(int8_t)((id0 >> sh)     & 0xffu)) * sx;
            t01 += (float)((int)(int8_t)((id0 >> (sh+8)) & 0xffu)) * sx;
            t10 += (float)((int)(int8_t)((id1 >> sh)     & 0xffu)) * sx;
            t11 += (float)((int)(int8_t)((id1 >> (sh+8)) & 0xffu)) * sx;
        }
        dstp[(n*CC + o0    )*HW + hw0] = t00;
        dstp[(n*CC + o0 + 1)*HW + hw0] = t01;
        dstp[(n*CC + o0    )*HW + hw1] = t10;
        dstp[(n*CC + o0 + 1)*HW + hw1] = t11;
        mx = fmaxf(mx, fmaxf(fmaxf(t00, t01), fmaxf(t10, t11)));
    }
    mx = warpMaxPos(mx);
    if (lane == 0) smx[wid] = mx;
    __syncthreads();
    if (tid == 0) {
        float m = smx[0];
        #pragma unroll
        for (int i = 1; i < 7; i++) m = fmaxf(m, smx[i]);
        atomicMaxF((PASS == 1) ? &g_max_r1 : &g_max_r2, m);
    }
}

// ---------------- HM_act / HM_energy from factorized stats ----------------
__device__ __forceinline__ long long energyFor(const int* stats, const int* wsum, int cb) {
    int S   = stats[        cb];
    int r0  = stats[ 512  + cb];
    int r55 = stats[1024  + cb];
    int c0  = stats[1536  + cb];
    int c55 = stats[2048  + cb];
    int s00 = stats[2560  + cb];
    int s0b = stats[3072  + cb];
    int sb0 = stats[3584  + cb];
    int sbb = stats[4096  + cb];
    long long en = 0;
    #pragma unroll
    for (int kh = 0; kh < 3; kh++) {
        #pragma unroll
        for (int kw = 0; kw < 3; kw++) {
            int xs = S;
            if (kh == 2) xs -= r0;  else if (kh == 0) xs -= r55;
            if (kw == 2) xs -= c0;  else if (kw == 0) xs -= c55;
            if (kh == 2 && kw == 2) xs += s00;
            if (kh == 2 && kw == 0) xs += s0b;
            if (kh == 0 && kw == 2) xs += sb0;
            if (kh == 0 && kw == 0) xs += sbb;
            en += (long long)wsum[cb*9 + kh*3 + kw] * (long long)xs;
        }
    }
    return en;
}

// ---------------- final QuantReLU on d_out (in place) + finalize (block 1568) --
__global__ void __launch_bounds__(256) finalQuantFin(float* __restrict__ out) {
    cudaGridDependencySynchronize();
    if (blockIdx.x == 1568) {
        int t = threadIdx.x;
        long long act = 0, en = 0;
        for (int cb = t; cb < 512; cb += 256) {
            act += (long long)g_stats1[cb] + (long long)g_stats2[cb];
            en  += energyFor(g_stats1, g_wsum1, cb) + energyFor(g_stats2, g_wsum2, cb);
        }
        __shared__ long long sa[256], se[256];
        sa[t] = act; se[t] = en;
        __syncthreads();
        for (int step = 128; step; step >>= 1) {
            if (t < step) { sa[t] += sa[t + step]; se[t] += se[t + step]; }
            __syncthreads();
        }
        if (t == 0) {
            out[NN*CC*HW    ] = (float)sa[0];   // HM_act
            out[NN*CC*HW + 1] = (float)se[0];   // HM_energy
        }
        return;
    }
    float s = g_max_r2 * (1.f/255.f);
    float sinv = 1.0f / s;
    float4* o4 = (float4*)out;
    int base = blockIdx.x*256 + threadIdx.x;
    #pragma unroll
    for (int it = 0; it < 2; it++) {
        int i = base + it*401408;
        float4 v = o4[i];
        v.x = (float)::min(255, __float2int_rn(fmaxf(v.x, 0.f) * sinv)) * s;
        v.y = (float)::min(255, __float2int_rn(fmaxf(v.y, 0.f) * sinv)) * s;
        v.z = (float)::min(255, __float2int_rn(fmaxf(v.z, 0.f) * sinv)) * s;
        v.w = (float)::min(255, __float2int_rn(fmaxf(v.w, 0.f) * sinv)) * s;
        o4[i] = v;
    }
}

// ---------------- PDL launch helper ----------------
template <typename F, typename... Args>
static inline void launchPDL(F f, unsigned grid, unsigned block, unsigned smem, Args... args) {
    cudaLaunchConfig_t cfg = {};
    cfg.gridDim  = dim3(grid, 1, 1);
    cfg.blockDim = dim3(block, 1, 1);
    cfg.dynamicSmemBytes = smem;
    cudaLaunchAttribute at[1];
    at[0].id = cudaLaunchAttributeProgrammaticStreamSerialization;
    at[0].val.programmaticStreamSerializationAllowed = 1;
    cfg.attrs = at;
    cfg.numAttrs = 1;
    cfg.stream = 0;
    cudaLaunchKernelEx(&cfg, f, args...);
}

#define CONV_SMEM ((9344 + 3712) * 4)

// ---------------- launch ----------------
extern "C" void kernel_launch(void* const* d_in, const int* in_sizes, int n_in,
                              void* d_out, int out_size) {
    const float* x  = (const float*)d_in[0];
    const float* w1 = (const float*)d_in[1];
    const float* w2 = (const float*)d_in[2];
    const float* g1 = (const float*)d_in[3];
    const float* b1 = (const float*)d_in[4];
    const float* m1 = (const float*)d_in[5];
    const float* v1 = (const float*)d_in[6];
    const float* g2 = (const float*)d_in[7];
    const float* b2 = (const float*)d_in[8];
    const float* m2 = (const float*)d_in[9];
    const float* v2 = (const float*)d_in[10];
    float* out = (float*)d_out;

    cudaFuncSetAttribute(convKernel<1>, cudaFuncAttributeMaxDynamicSharedMemorySize, CONV_SMEM);
    cudaFuncSetAttribute(convKernel<2>, cudaFuncAttributeMaxDynamicSharedMemorySize, CONV_SMEM);

    reduceA<<<515, 256>>>((const float4*)x, w1, w2);
    launchPDL(quantStatsKernel<1>, 548, 256, 0, x, w1, w2);
    launchPDL(convKernel<1>, 448, 224, CONV_SMEM, g1, b1, m1, v1, (float*)nullptr);
    launchPDL(quantStatsKernel<2>, 512, 256, 0, (const float*)nullptr, (const float*)nullptr, (const float*)nullptr);
    launchPDL(convKernel<2>, 448, 224, CONV_SMEM, g2, b2, m2, v2, out);
    launchPDL(finalQuantFin, 1569, 256, 0, out);
}